// round 1
// baseline (speedup 1.0000x reference)
#include <cuda_runtime.h>
#include <cuda_bf16.h>
#include <cstddef>

#define BATCH 8
#define TENC 2048
#define TDEC 512
#define DIM  1024
#define NEG_BIG 1e20f

// ---------------------------------------------------------------------------
// GEMM1: S[b,t,u] = sum_d enc[b,t,d] * dec[b,u,d]  - (1-mask[b,t])*NEG_BIG
// A (enc) row-major [TENC, DIM], B (dec) row-major [TDEC, DIM]; C = A @ B^T
// 128x128 tile, BK=16, 256 threads, 8x8 per thread.
// ---------------------------------------------------------------------------
__global__ __launch_bounds__(256) void gemm1_kernel(
    const float* __restrict__ enc, const float* __restrict__ dec,
    const int* __restrict__ enc_mask, float* __restrict__ S)
{
    const int b  = blockIdx.z;
    const int m0 = blockIdx.y * 128;   // t tile
    const int n0 = blockIdx.x * 128;   // u tile

    const float* A  = enc + (size_t)b * TENC * DIM;
    const float* Bm = dec + (size_t)b * TDEC * DIM;
    float*       C  = S   + (size_t)b * TENC * TDEC;
    const int*   mk = enc_mask + b * TENC;

    __shared__ float As[16][128];
    __shared__ float Bs[16][128];

    const int tid = threadIdx.x;
    const int tx  = tid % 16;          // n micro
    const int ty  = tid / 16;          // m micro

    float acc[8][8];
    #pragma unroll
    for (int i = 0; i < 8; i++)
        #pragma unroll
        for (int j = 0; j < 8; j++) acc[i][j] = 0.f;

    const int lr = tid / 4;            // 0..63 row
    const int lc = tid % 4;            // 0..3 k-float4

    for (int k0 = 0; k0 < DIM; k0 += 16) {
        #pragma unroll
        for (int p = 0; p < 2; p++) {
            int row = lr + p * 64;
            float4 v = *(const float4*)(A  + (size_t)(m0 + row) * DIM + k0 + lc * 4);
            As[lc*4+0][row] = v.x; As[lc*4+1][row] = v.y;
            As[lc*4+2][row] = v.z; As[lc*4+3][row] = v.w;
            float4 w = *(const float4*)(Bm + (size_t)(n0 + row) * DIM + k0 + lc * 4);
            Bs[lc*4+0][row] = w.x; Bs[lc*4+1][row] = w.y;
            Bs[lc*4+2][row] = w.z; Bs[lc*4+3][row] = w.w;
        }
        __syncthreads();

        #pragma unroll
        for (int kk = 0; kk < 16; kk++) {
            float ar[8], br[8];
            #pragma unroll
            for (int i = 0; i < 4; i++) {
                ((float4*)ar)[0] = *(const float4*)&As[kk][ty*8];
                ((float4*)ar)[1] = *(const float4*)&As[kk][ty*8+4];
                ((float4*)br)[0] = *(const float4*)&Bs[kk][tx*8];
                ((float4*)br)[1] = *(const float4*)&Bs[kk][tx*8+4];
                break;
            }
            #pragma unroll
            for (int i = 0; i < 8; i++)
                #pragma unroll
                for (int j = 0; j < 8; j++)
                    acc[i][j] = fmaf(ar[i], br[j], acc[i][j]);
        }
        __syncthreads();
    }

    #pragma unroll
    for (int i = 0; i < 8; i++) {
        int m = m0 + ty * 8 + i;
        float bias = (1.0f - (float)mk[m]) * NEG_BIG;
        float out[8];
        #pragma unroll
        for (int j = 0; j < 8; j++) out[j] = acc[i][j] - bias;
        float* crow = C + (size_t)m * TDEC + n0 + tx * 8;
        *(float4*)(crow)     = *(float4*)&out[0];
        *(float4*)(crow + 4) = *(float4*)&out[4];
    }
}

// ---------------------------------------------------------------------------
// Softmax over t (axis Tenc) for each (b,u) column, in place on S.
// Block = 128 threads, each owns one u column. 3 passes.
// ---------------------------------------------------------------------------
__global__ __launch_bounds__(128) void softmax_kernel(float* __restrict__ S)
{
    const int b = blockIdx.y;
    const int u = blockIdx.x * 128 + threadIdx.x;
    float* col = S + (size_t)b * TENC * TDEC + u;

    float m = -3.4e38f;
    for (int t = 0; t < TENC; t++)
        m = fmaxf(m, col[(size_t)t * TDEC]);

    float s = 0.f;
    for (int t = 0; t < TENC; t++)
        s += __expf(col[(size_t)t * TDEC] - m);

    float inv = 1.0f / s;
    for (int t = 0; t < TENC; t++) {
        size_t idx = (size_t)t * TDEC;
        col[idx] = __expf(col[idx] - m) * inv;
    }
}

// ---------------------------------------------------------------------------
// GEMM2: ctx[b,u,d] = sum_t S[b,t,u] * enc[b,t,d]
// A[u,k] = S[k*TDEC + u] (column access, contiguous in u), B[k,d] = enc.
// ---------------------------------------------------------------------------
__global__ __launch_bounds__(256) void gemm2_kernel(
    const float* __restrict__ S, const float* __restrict__ enc,
    float* __restrict__ ctx)
{
    const int b  = blockIdx.z;
    const int u0 = blockIdx.y * 128;
    const int d0 = blockIdx.x * 128;

    const float* Sb = S   + (size_t)b * TENC * TDEC;
    const float* Eb = enc + (size_t)b * TENC * DIM;
    float*       C  = ctx + (size_t)b * TDEC * DIM;

    __shared__ float As[16][128];   // [k][u]
    __shared__ float Bs[16][128];   // [k][d]

    const int tid = threadIdx.x;
    const int tx  = tid % 16;       // d micro
    const int ty  = tid / 16;       // u micro

    float acc[8][8];
    #pragma unroll
    for (int i = 0; i < 8; i++)
        #pragma unroll
        for (int j = 0; j < 8; j++) acc[i][j] = 0.f;

    const int ak  = tid / 32;       // 0..7 (k row, +8 second pass)
    const int av4 = tid % 32;       // float4 index within 128-wide row

    for (int k0 = 0; k0 < TENC; k0 += 16) {
        #pragma unroll
        for (int p = 0; p < 2; p++) {
            int kk = ak + p * 8;
            float4 v = *(const float4*)(Sb + (size_t)(k0 + kk) * TDEC + u0 + av4 * 4);
            *(float4*)&As[kk][av4 * 4] = v;
            float4 w = *(const float4*)(Eb + (size_t)(k0 + kk) * DIM + d0 + av4 * 4);
            *(float4*)&Bs[kk][av4 * 4] = w;
        }
        __syncthreads();

        #pragma unroll
        for (int kk = 0; kk < 16; kk++) {
            float ar[8], br[8];
            ((float4*)ar)[0] = *(const float4*)&As[kk][ty*8];
            ((float4*)ar)[1] = *(const float4*)&As[kk][ty*8+4];
            ((float4*)br)[0] = *(const float4*)&Bs[kk][tx*8];
            ((float4*)br)[1] = *(const float4*)&Bs[kk][tx*8+4];
            #pragma unroll
            for (int i = 0; i < 8; i++)
                #pragma unroll
                for (int j = 0; j < 8; j++)
                    acc[i][j] = fmaf(ar[i], br[j], acc[i][j]);
        }
        __syncthreads();
    }

    #pragma unroll
    for (int i = 0; i < 8; i++) {
        int u = u0 + ty * 8 + i;
        float* crow = C + (size_t)u * DIM + d0 + tx * 8;
        *(float4*)(crow)     = *(float4*)&acc[i][0];
        *(float4*)(crow + 4) = *(float4*)&acc[i][4];
    }
}

// ---------------------------------------------------------------------------
extern "C" void kernel_launch(void* const* d_in, const int* in_sizes, int n_in,
                              void* d_out, int out_size)
{
    const float* enc      = (const float*)d_in[0];
    const int*   enc_mask = (const int*)  d_in[1];
    const float* dec      = (const float*)d_in[2];

    float* ctx = (float*)d_out;                               // [B, TDEC, DIM]
    float* S   = ctx + (size_t)BATCH * TDEC * DIM;            // [B, TENC, TDEC]

    gemm1_kernel<<<dim3(TDEC/128, TENC/128, BATCH), 256>>>(enc, dec, enc_mask, S);
    softmax_kernel<<<dim3(TDEC/128, BATCH), 128>>>(S);
    gemm2_kernel<<<dim3(DIM/128, TDEC/128, BATCH), 256>>>(S, enc, ctx);
}

// round 3
// speedup vs baseline: 2.4821x; 2.4821x over previous
#include <cuda_runtime.h>
#include <cuda_bf16.h>
#include <cstdint>
#include <cstddef>

#define BATCH 8
#define TENC 2048
#define TDEC 512
#define DIM  1024
#define NEG_BIG 1e20f

// ---------------------------------------------------------------------------
// Scratch (static device arrays — no allocation allowed)
// ---------------------------------------------------------------------------
__device__ __nv_bfloat16 g_eh[(size_t)BATCH * TENC * DIM];   // enc hi
__device__ __nv_bfloat16 g_el[(size_t)BATCH * TENC * DIM];   // enc lo
__device__ __nv_bfloat16 g_dh[(size_t)BATCH * TDEC * DIM];   // dec hi
__device__ __nv_bfloat16 g_dl[(size_t)BATCH * TDEC * DIM];   // dec lo
__device__ __nv_bfloat16 g_ph[(size_t)BATCH * TENC * TDEC];  // scores hi
__device__ __nv_bfloat16 g_pl[(size_t)BATCH * TENC * TDEC];  // scores lo

// ---------------------------------------------------------------------------
// helpers
// ---------------------------------------------------------------------------
__device__ __forceinline__ uint32_t smem_u32(const void* p) {
    return (uint32_t)__cvta_generic_to_shared(p);
}
__device__ __forceinline__ void cpa16(uint32_t s, const void* g) {
    asm volatile("cp.async.cg.shared.global [%0], [%1], 16;\n" :: "r"(s), "l"(g));
}
__device__ __forceinline__ void cpa_commit_wait() {
    asm volatile("cp.async.commit_group;\n");
    asm volatile("cp.async.wait_group 0;\n");
}
__device__ __forceinline__ void ldsm4(uint32_t* r, uint32_t a) {
    asm volatile("ldmatrix.sync.aligned.m8n8.x4.shared.b16 {%0,%1,%2,%3}, [%4];\n"
                 : "=r"(r[0]), "=r"(r[1]), "=r"(r[2]), "=r"(r[3]) : "r"(a));
}
__device__ __forceinline__ void ldsm4t(uint32_t* r, uint32_t a) {
    asm volatile("ldmatrix.sync.aligned.m8n8.x4.trans.shared.b16 {%0,%1,%2,%3}, [%4];\n"
                 : "=r"(r[0]), "=r"(r[1]), "=r"(r[2]), "=r"(r[3]) : "r"(a));
}
__device__ __forceinline__ void mma16816(float* c, const uint32_t* a, uint32_t b0, uint32_t b1) {
    asm volatile(
        "mma.sync.aligned.m16n8k16.row.col.f32.bf16.bf16.f32 "
        "{%0,%1,%2,%3},{%4,%5,%6,%7},{%8,%9},{%0,%1,%2,%3};\n"
        : "+f"(c[0]), "+f"(c[1]), "+f"(c[2]), "+f"(c[3])
        : "r"(a[0]), "r"(a[1]), "r"(a[2]), "r"(a[3]), "r"(b0), "r"(b1));
}

// ---------------------------------------------------------------------------
// split f32 -> bf16 hi + bf16 lo
// ---------------------------------------------------------------------------
__device__ __forceinline__ void split_body(const float* __restrict__ x,
                                           __nv_bfloat16* __restrict__ h,
                                           __nv_bfloat16* __restrict__ l, int n4) {
    int stride = gridDim.x * blockDim.x;
    for (int i = blockIdx.x * blockDim.x + threadIdx.x; i < n4; i += stride) {
        float4 v = ((const float4*)x)[i];
        __nv_bfloat16 h0 = __float2bfloat16(v.x);
        __nv_bfloat16 h1 = __float2bfloat16(v.y);
        __nv_bfloat16 h2 = __float2bfloat16(v.z);
        __nv_bfloat16 h3 = __float2bfloat16(v.w);
        __nv_bfloat16 l0 = __float2bfloat16(v.x - __bfloat162float(h0));
        __nv_bfloat16 l1 = __float2bfloat16(v.y - __bfloat162float(h1));
        __nv_bfloat16 l2 = __float2bfloat16(v.z - __bfloat162float(h2));
        __nv_bfloat16 l3 = __float2bfloat16(v.w - __bfloat162float(h3));
        __nv_bfloat162 hA = {h0, h1}, hB = {h2, h3}, lA = {l0, l1}, lB = {l2, l3};
        uint2 hv = {*(uint32_t*)&hA, *(uint32_t*)&hB};
        uint2 lv = {*(uint32_t*)&lA, *(uint32_t*)&lB};
        ((uint2*)h)[i] = hv;
        ((uint2*)l)[i] = lv;
    }
}

__global__ void split_enc_kernel(const float* __restrict__ x) {
    split_body(x, g_eh, g_el, (int)((size_t)BATCH * TENC * DIM / 4));
}
__global__ void split_dec_kernel(const float* __restrict__ x) {
    split_body(x, g_dh, g_dl, (int)((size_t)BATCH * TDEC * DIM / 4));
}

// ---------------------------------------------------------------------------
// GEMM1: S[b,t,u] = sum_d enc[t,d]*dec[u,d] - (1-mask[t])*NEG_BIG
// bf16x3 via mma.sync m16n8k16. BM=BN=128, BK=32, 8 warps (2m x 4n), 64x32/warp.
// smem stride 40 bf16 (80 B) -> conflict-free ldmatrix.
// ---------------------------------------------------------------------------
#define G1_STRIDE 40

__global__ __launch_bounds__(256, 2) void gemm1_kernel(
    const int* __restrict__ enc_mask, float* __restrict__ S)
{
    const int b  = blockIdx.z;
    const int m0 = blockIdx.y * 128;   // t
    const int n0 = blockIdx.x * 128;   // u

    const __nv_bfloat16* Ah = g_eh + (size_t)b * TENC * DIM;
    const __nv_bfloat16* Al = g_el + (size_t)b * TENC * DIM;
    const __nv_bfloat16* Bh = g_dh + (size_t)b * TDEC * DIM;
    const __nv_bfloat16* Bl = g_dl + (size_t)b * TDEC * DIM;
    const int* mk = enc_mask + b * TENC;
    float* Sp = S + (size_t)b * TENC * TDEC;

    __shared__ __align__(16) __nv_bfloat16 sAh[128 * G1_STRIDE];
    __shared__ __align__(16) __nv_bfloat16 sAl[128 * G1_STRIDE];
    __shared__ __align__(16) __nv_bfloat16 sBh[128 * G1_STRIDE];
    __shared__ __align__(16) __nv_bfloat16 sBl[128 * G1_STRIDE];

    const int tid  = threadIdx.x;
    const int lane = tid & 31;
    const int wid  = tid >> 5;
    const int m_off = (wid & 1) * 64;
    const int n_off = (wid >> 1) * 32;

    const uint32_t bAh = smem_u32(sAh), bAl = smem_u32(sAl);
    const uint32_t bBh = smem_u32(sBh), bBl = smem_u32(sBl);

    const int lrow = tid >> 2;        // 0..63 (+64 second half)
    const int lc   = tid & 3;         // uint4 within 64B row-chunk

    const uint32_t aBase = (uint32_t)((m_off + (lane & 15)) * 80 + (lane >> 4) * 16);
    const uint32_t bBase = (uint32_t)((n_off + (lane & 7) + ((lane >> 4) << 3)) * 80
                                      + ((lane >> 3) & 1) * 16);

    float acc[4][4][4];
    #pragma unroll
    for (int i = 0; i < 4; i++)
        #pragma unroll
        for (int j = 0; j < 4; j++)
            #pragma unroll
            for (int k = 0; k < 4; k++) acc[i][j][k] = 0.f;

    for (int k0 = 0; k0 < DIM; k0 += 32) {
        __syncthreads();
        #pragma unroll
        for (int j = 0; j < 2; j++) {
            int row = lrow + j * 64;
            uint32_t so = (uint32_t)(row * 80 + lc * 16);
            size_t goA = (size_t)(m0 + row) * DIM + k0 + lc * 8;
            size_t goB = (size_t)(n0 + row) * DIM + k0 + lc * 8;
            cpa16(bAh + so, Ah + goA);
            cpa16(bAl + so, Al + goA);
            cpa16(bBh + so, Bh + goB);
            cpa16(bBl + so, Bl + goB);
        }
        cpa_commit_wait();
        __syncthreads();

        #pragma unroll
        for (int ks = 0; ks < 2; ks++) {
            uint32_t koff = (uint32_t)(ks * 32);
            uint32_t ah[4][4], bh[2][4];
            #pragma unroll
            for (int im = 0; im < 4; im++) ldsm4(ah[im], bAh + aBase + im * 1280 + koff);
            #pragma unroll
            for (int p = 0; p < 2; p++)   ldsm4(bh[p], bBh + bBase + p * 1280 + koff);
            #pragma unroll
            for (int im = 0; im < 4; im++)
                #pragma unroll
                for (int in = 0; in < 4; in++)
                    mma16816(acc[im][in], ah[im], bh[in >> 1][(in & 1) * 2], bh[in >> 1][(in & 1) * 2 + 1]);

            uint32_t bl[2][4];
            #pragma unroll
            for (int p = 0; p < 2; p++) ldsm4(bl[p], bBl + bBase + p * 1280 + koff);
            #pragma unroll
            for (int im = 0; im < 4; im++)
                #pragma unroll
                for (int in = 0; in < 4; in++)
                    mma16816(acc[im][in], ah[im], bl[in >> 1][(in & 1) * 2], bl[in >> 1][(in & 1) * 2 + 1]);

            uint32_t al[4][4];
            #pragma unroll
            for (int im = 0; im < 4; im++) ldsm4(al[im], bAl + aBase + im * 1280 + koff);
            #pragma unroll
            for (int im = 0; im < 4; im++)
                #pragma unroll
                for (int in = 0; in < 4; in++)
                    mma16816(acc[im][in], al[im], bh[in >> 1][(in & 1) * 2], bh[in >> 1][(in & 1) * 2 + 1]);
        }
    }

    #pragma unroll
    for (int im = 0; im < 4; im++) {
        int tr = m0 + m_off + im * 16 + (lane >> 2);
        float bias0 = (1.0f - (float)mk[tr])     * NEG_BIG;
        float bias1 = (1.0f - (float)mk[tr + 8]) * NEG_BIG;
        #pragma unroll
        for (int in = 0; in < 4; in++) {
            int col = n0 + n_off + in * 8 + (lane & 3) * 2;
            float2 v0 = {acc[im][in][0] - bias0, acc[im][in][1] - bias0};
            float2 v1 = {acc[im][in][2] - bias1, acc[im][in][3] - bias1};
            *(float2*)&Sp[(size_t)tr * TDEC + col]       = v0;
            *(float2*)&Sp[(size_t)(tr + 8) * TDEC + col] = v1;
        }
    }
}

// ---------------------------------------------------------------------------
// Softmax over t, per (b,u) column. Block = 16 u x 16 t-slices.
// ---------------------------------------------------------------------------
__global__ __launch_bounds__(256) void softmax_kernel(float* __restrict__ S)
{
    const int b  = blockIdx.y;
    const int ux = threadIdx.x;            // 0..15
    const int tz = threadIdx.y;            // 0..15
    const int u  = blockIdx.x * 16 + ux;

    size_t base = (size_t)b * TENC * TDEC + u;
    float* col = S + base;
    __nv_bfloat16* ph = g_ph + base;
    __nv_bfloat16* pl = g_pl + base;

    __shared__ float red[16][17];

    float m = -3.4e38f;
    for (int t = tz; t < TENC; t += 16)
        m = fmaxf(m, col[(size_t)t * TDEC]);
    red[tz][ux] = m;
    __syncthreads();
    #pragma unroll
    for (int s = 8; s > 0; s >>= 1) {
        if (tz < s) red[tz][ux] = fmaxf(red[tz][ux], red[tz + s][ux]);
        __syncthreads();
    }
    m = red[0][ux];
    __syncthreads();

    float sum = 0.f;
    for (int t = tz; t < TENC; t += 16) {
        float e = __expf(col[(size_t)t * TDEC] - m);
        col[(size_t)t * TDEC] = e;
        sum += e;
    }
    red[tz][ux] = sum;
    __syncthreads();
    #pragma unroll
    for (int s = 8; s > 0; s >>= 1) {
        if (tz < s) red[tz][ux] += red[tz + s][ux];
        __syncthreads();
    }
    float inv = 1.0f / red[0][ux];

    for (int t = tz; t < TENC; t += 16) {
        size_t idx = (size_t)t * TDEC;
        float p = col[idx] * inv;
        col[idx] = p;
        __nv_bfloat16 hb = __float2bfloat16(p);
        ph[idx] = hb;
        pl[idx] = __float2bfloat16(p - __bfloat162float(hb));
    }
}

// ---------------------------------------------------------------------------
// GEMM2: ctx[b,u,d] = sum_t p[t,u] * enc[t,d]
// A = p stored [t][u] -> ldmatrix.trans ; B = enc stored [t][d] -> ldmatrix.trans
// BM=128(u), BN=128(d), BK=32(t). smem stride 136 bf16 (272 B).
// ---------------------------------------------------------------------------
#define G2_STRIDE 136

__global__ __launch_bounds__(256, 2) void gemm2_kernel(float* __restrict__ ctx)
{
    const int b  = blockIdx.z;
    const int u0 = blockIdx.y * 128;
    const int d0 = blockIdx.x * 128;

    const __nv_bfloat16* Ph = g_ph + (size_t)b * TENC * TDEC;
    const __nv_bfloat16* Pl = g_pl + (size_t)b * TENC * TDEC;
    const __nv_bfloat16* Eh = g_eh + (size_t)b * TENC * DIM;
    const __nv_bfloat16* El = g_el + (size_t)b * TENC * DIM;
    float* C = ctx + (size_t)b * TDEC * DIM;

    __shared__ __align__(16) __nv_bfloat16 sPh[32 * G2_STRIDE];
    __shared__ __align__(16) __nv_bfloat16 sPl[32 * G2_STRIDE];
    __shared__ __align__(16) __nv_bfloat16 sEh[32 * G2_STRIDE];
    __shared__ __align__(16) __nv_bfloat16 sEl[32 * G2_STRIDE];

    const int tid  = threadIdx.x;
    const int lane = tid & 31;
    const int wid  = tid >> 5;
    const int m_off = (wid & 1) * 64;   // u
    const int n_off = (wid >> 1) * 32;  // d

    const uint32_t bPh = smem_u32(sPh), bPl = smem_u32(sPl);
    const uint32_t bEh = smem_u32(sEh), bEl = smem_u32(sEl);

    const int lrow = tid >> 4;   // 0..15 (+16)
    const int lc   = tid & 15;   // uint4 within 256B row

    const uint32_t aBase = (uint32_t)(((lane & 7) + ((lane >> 4) << 3)) * 272
                                      + (m_off + ((lane >> 3) & 1) * 8) * 2);
    const uint32_t bBase = (uint32_t)(((lane & 7) + (((lane >> 3) & 1) << 3)) * 272
                                      + (n_off + (lane >> 4) * 8) * 2);

    float acc[4][4][4];
    #pragma unroll
    for (int i = 0; i < 4; i++)
        #pragma unroll
        for (int j = 0; j < 4; j++)
            #pragma unroll
            for (int k = 0; k < 4; k++) acc[i][j][k] = 0.f;

    for (int k0 = 0; k0 < TENC; k0 += 32) {
        __syncthreads();
        #pragma unroll
        for (int j = 0; j < 2; j++) {
            int row = lrow + j * 16;
            uint32_t so = (uint32_t)(row * 272 + lc * 16);
            size_t goP = (size_t)(k0 + row) * TDEC + u0 + lc * 8;
            size_t goE = (size_t)(k0 + row) * DIM + d0 + lc * 8;
            cpa16(bPh + so, Ph + goP);
            cpa16(bPl + so, Pl + goP);
            cpa16(bEh + so, Eh + goE);
            cpa16(bEl + so, El + goE);
        }
        cpa_commit_wait();
        __syncthreads();

        #pragma unroll
        for (int ks = 0; ks < 2; ks++) {
            uint32_t koff = (uint32_t)(ks * 16 * 272);
            uint32_t ah[4][4], bh[2][4];
            #pragma unroll
            for (int im = 0; im < 4; im++) ldsm4t(ah[im], bPh + aBase + im * 32 + koff);
            #pragma unroll
            for (int p = 0; p < 2; p++)   ldsm4t(bh[p], bEh + bBase + p * 32 + koff);
            #pragma unroll
            for (int im = 0; im < 4; im++)
                #pragma unroll
                for (int in = 0; in < 4; in++)
                    mma16816(acc[im][in], ah[im], bh[in >> 1][(in & 1) * 2], bh[in >> 1][(in & 1) * 2 + 1]);

            uint32_t bl[2][4];
            #pragma unroll
            for (int p = 0; p < 2; p++) ldsm4t(bl[p], bEl + bBase + p * 32 + koff);
            #pragma unroll
            for (int im = 0; im < 4; im++)
                #pragma unroll
                for (int in = 0; in < 4; in++)
                    mma16816(acc[im][in], ah[im], bl[in >> 1][(in & 1) * 2], bl[in >> 1][(in & 1) * 2 + 1]);

            uint32_t al[4][4];
            #pragma unroll
            for (int im = 0; im < 4; im++) ldsm4t(al[im], bPl + aBase + im * 32 + koff);
            #pragma unroll
            for (int im = 0; im < 4; im++)
                #pragma unroll
                for (int in = 0; in < 4; in++)
                    mma16816(acc[im][in], al[im], bh[in >> 1][(in & 1) * 2], bh[in >> 1][(in & 1) * 2 + 1]);
        }
    }

    #pragma unroll
    for (int im = 0; im < 4; im++) {
        int ur = u0 + m_off + im * 16 + (lane >> 2);
        #pragma unroll
        for (int in = 0; in < 4; in++) {
            int col = d0 + n_off + in * 8 + (lane & 3) * 2;
            float2 v0 = {acc[im][in][0], acc[im][in][1]};
            float2 v1 = {acc[im][in][2], acc[im][in][3]};
            *(float2*)&C[(size_t)ur * DIM + col]       = v0;
            *(float2*)&C[(size_t)(ur + 8) * DIM + col] = v1;
        }
    }
}

// ---------------------------------------------------------------------------
extern "C" void kernel_launch(void* const* d_in, const int* in_sizes, int n_in,
                              void* d_out, int out_size)
{
    const float* enc      = (const float*)d_in[0];
    const int*   enc_mask = (const int*)  d_in[1];
    const float* dec      = (const float*)d_in[2];

    float* ctx = (float*)d_out;                      // [B, TDEC, DIM]
    float* S   = ctx + (size_t)BATCH * TDEC * DIM;   // [B, TENC, TDEC]

    split_enc_kernel<<<1024, 256>>>(enc);
    split_dec_kernel<<<512, 256>>>(dec);
    gemm1_kernel<<<dim3(TDEC / 128, TENC / 128, BATCH), 256>>>(enc_mask, S);
    softmax_kernel<<<dim3(TDEC / 16, BATCH), dim3(16, 16)>>>(S);
    gemm2_kernel<<<dim3(DIM / 128, TDEC / 128, BATCH), 256>>>(ctx);
}

// round 6
// speedup vs baseline: 2.7645x; 1.1138x over previous
#include <cuda_runtime.h>
#include <cuda_bf16.h>
#include <cstdint>
#include <cstddef>

#define BATCH 8
#define TENC 2048
#define TDEC 512
#define DIM  1024
#define NEG_BIG 1e20f

// ---------------------------------------------------------------------------
// Scratch (static device arrays — no allocation allowed)
// ---------------------------------------------------------------------------
__device__ __nv_bfloat16 g_eh[(size_t)BATCH * TENC * DIM];   // enc hi [b][t][d]
__device__ __nv_bfloat16 g_el[(size_t)BATCH * TENC * DIM];   // enc lo
__device__ __nv_bfloat16 g_dh[(size_t)BATCH * TDEC * DIM];   // dec hi [b][u][d]
__device__ __nv_bfloat16 g_dl[(size_t)BATCH * TDEC * DIM];   // dec lo
__device__ __nv_bfloat16 g_ph[(size_t)BATCH * TENC * TDEC];  // scores hi [b][t][u]
__device__ __nv_bfloat16 g_pl[(size_t)BATCH * TENC * TDEC];  // scores lo
// softmax partials
__device__ float g_cm[BATCH * 8 * TDEC];
__device__ float g_cs[BATCH * 8 * TDEC];
__device__ float g_Mx[BATCH * TDEC];
__device__ float g_Iv[BATCH * TDEC];

// ---------------------------------------------------------------------------
// helpers
// ---------------------------------------------------------------------------
__device__ __forceinline__ uint32_t smem_u32(const void* p) {
    return (uint32_t)__cvta_generic_to_shared(p);
}
__device__ __forceinline__ void cpa16(uint32_t s, const void* g) {
    asm volatile("cp.async.cg.shared.global [%0], [%1], 16;\n" :: "r"(s), "l"(g));
}
__device__ __forceinline__ void cpa_commit() {
    asm volatile("cp.async.commit_group;\n");
}
__device__ __forceinline__ void cpa_wait1() {
    asm volatile("cp.async.wait_group 1;\n");
}
__device__ __forceinline__ void cpa_wait0() {
    asm volatile("cp.async.wait_group 0;\n");
}
__device__ __forceinline__ void ldsm4(uint32_t* r, uint32_t a) {
    asm volatile("ldmatrix.sync.aligned.m8n8.x4.shared.b16 {%0,%1,%2,%3}, [%4];\n"
                 : "=r"(r[0]), "=r"(r[1]), "=r"(r[2]), "=r"(r[3]) : "r"(a));
}
__device__ __forceinline__ void ldsm4t(uint32_t* r, uint32_t a) {
    asm volatile("ldmatrix.sync.aligned.m8n8.x4.trans.shared.b16 {%0,%1,%2,%3}, [%4];\n"
                 : "=r"(r[0]), "=r"(r[1]), "=r"(r[2]), "=r"(r[3]) : "r"(a));
}
__device__ __forceinline__ void mma16816(float* c, const uint32_t* a, uint32_t b0, uint32_t b1) {
    asm volatile(
        "mma.sync.aligned.m16n8k16.row.col.f32.bf16.bf16.f32 "
        "{%0,%1,%2,%3},{%4,%5,%6,%7},{%8,%9},{%0,%1,%2,%3};\n"
        : "+f"(c[0]), "+f"(c[1]), "+f"(c[2]), "+f"(c[3])
        : "r"(a[0]), "r"(a[1]), "r"(a[2]), "r"(a[3]), "r"(b0), "r"(b1));
}

// ---------------------------------------------------------------------------
// input splits: f32 -> bf16 hi + lo
// ---------------------------------------------------------------------------
__device__ __forceinline__ void split_body(const float* __restrict__ x,
                                           __nv_bfloat16* __restrict__ h,
                                           __nv_bfloat16* __restrict__ l, int n4) {
    int stride = gridDim.x * blockDim.x;
    for (int i = blockIdx.x * blockDim.x + threadIdx.x; i < n4; i += stride) {
        float4 v = ((const float4*)x)[i];
        __nv_bfloat16 h0 = __float2bfloat16(v.x);
        __nv_bfloat16 h1 = __float2bfloat16(v.y);
        __nv_bfloat16 h2 = __float2bfloat16(v.z);
        __nv_bfloat16 h3 = __float2bfloat16(v.w);
        __nv_bfloat16 l0 = __float2bfloat16(v.x - __bfloat162float(h0));
        __nv_bfloat16 l1 = __float2bfloat16(v.y - __bfloat162float(h1));
        __nv_bfloat16 l2 = __float2bfloat16(v.z - __bfloat162float(h2));
        __nv_bfloat16 l3 = __float2bfloat16(v.w - __bfloat162float(h3));
        __nv_bfloat162 hA = {h0, h1}, hB = {h2, h3}, lA = {l0, l1}, lB = {l2, l3};
        uint2 hv = {*(uint32_t*)&hA, *(uint32_t*)&hB};
        uint2 lv = {*(uint32_t*)&lA, *(uint32_t*)&lB};
        ((uint2*)h)[i] = hv;
        ((uint2*)l)[i] = lv;
    }
}
__global__ void split_enc_kernel(const float* __restrict__ x) {
    split_body(x, g_eh, g_el, (int)((size_t)BATCH * TENC * DIM / 4));
}
__global__ void split_dec_kernel(const float* __restrict__ x) {
    split_body(x, g_dh, g_dl, (int)((size_t)BATCH * TDEC * DIM / 4));
}

// ---------------------------------------------------------------------------
// GEMM1: S[b,t,u] = sum_d enc[t,d]*dec[u,d] - (1-mask[t])*NEG_BIG
// bf16x3 mma.sync m16n8k16. BM=BN=128, BK=32, 8 warps (2m x 4n), 64x32/warp.
// Double-buffered cp.async pipeline (2 stages). smem row stride 80 B.
// ---------------------------------------------------------------------------
#define G1_BUF   10240            // one array, one stage: 128 rows * 80 B
#define G1_STAGE (4 * G1_BUF)     // Ah, Al, Bh, Bl
#define G1_DYN   (2 * G1_STAGE + 1024)

__global__ __launch_bounds__(256, 2) void gemm1_kernel(
    const int* __restrict__ enc_mask, float* __restrict__ S)
{
    extern __shared__ __align__(16) uint8_t dynsm[];
    const uint32_t dynb = (smem_u32(dynsm) + 1023u) & ~1023u;

    const int b  = blockIdx.z;
    const int m0 = blockIdx.y * 128;   // t
    const int n0 = blockIdx.x * 128;   // u

    const __nv_bfloat16* Ah = g_eh + (size_t)b * TENC * DIM;
    const __nv_bfloat16* Al = g_el + (size_t)b * TENC * DIM;
    const __nv_bfloat16* Bh = g_dh + (size_t)b * TDEC * DIM;
    const __nv_bfloat16* Bl = g_dl + (size_t)b * TDEC * DIM;
    const int* mk = enc_mask + b * TENC;
    float* Sp = S + (size_t)b * TENC * TDEC;

    const int tid  = threadIdx.x;
    const int lane = tid & 31;
    const int wid  = tid >> 5;
    const int m_off = (wid & 1) * 64;
    const int n_off = (wid >> 1) * 32;

    const int lrow = tid >> 2;        // 0..63 (+64 second half)
    const int lc   = tid & 3;

    const uint32_t aBase = (uint32_t)((m_off + (lane & 15)) * 80 + (lane >> 4) * 16);
    const uint32_t bBase = (uint32_t)((n_off + (lane & 7) + ((lane >> 4) << 3)) * 80
                                      + ((lane >> 3) & 1) * 16);

    float acc[4][4][4];
    #pragma unroll
    for (int i = 0; i < 4; i++)
        #pragma unroll
        for (int j = 0; j < 4; j++)
            #pragma unroll
            for (int k = 0; k < 4; k++) acc[i][j][k] = 0.f;

    const int NST = DIM / 32;

    auto load_stage = [&](int s, int buf) {
        const int k0 = s * 32;
        const uint32_t sb = dynb + (uint32_t)buf * G1_STAGE;
        #pragma unroll
        for (int j = 0; j < 2; j++) {
            int row = lrow + j * 64;
            uint32_t so = (uint32_t)(row * 80 + lc * 16);
            size_t goA = (size_t)(m0 + row) * DIM + k0 + lc * 8;
            size_t goB = (size_t)(n0 + row) * DIM + k0 + lc * 8;
            cpa16(sb + so,              Ah + goA);
            cpa16(sb + G1_BUF + so,     Al + goA);
            cpa16(sb + 2 * G1_BUF + so, Bh + goB);
            cpa16(sb + 3 * G1_BUF + so, Bl + goB);
        }
        cpa_commit();
    };

    load_stage(0, 0);
    load_stage(1, 1);

    for (int s = 0; s < NST; s++) {
        const int buf = s & 1;
        if (s == NST - 1) cpa_wait0(); else cpa_wait1();
        __syncthreads();

        const uint32_t bAh = dynb + (uint32_t)buf * G1_STAGE;
        const uint32_t bAl = bAh + G1_BUF;
        const uint32_t bBh = bAh + 2 * G1_BUF;
        const uint32_t bBl = bAh + 3 * G1_BUF;

        #pragma unroll
        for (int ks = 0; ks < 2; ks++) {
            uint32_t koff = (uint32_t)(ks * 32);
            uint32_t ah[4][4], bh[2][4];
            #pragma unroll
            for (int im = 0; im < 4; im++) ldsm4(ah[im], bAh + aBase + im * 1280 + koff);
            #pragma unroll
            for (int p = 0; p < 2; p++)   ldsm4(bh[p], bBh + bBase + p * 1280 + koff);
            #pragma unroll
            for (int im = 0; im < 4; im++)
                #pragma unroll
                for (int in = 0; in < 4; in++)
                    mma16816(acc[im][in], ah[im], bh[in >> 1][(in & 1) * 2], bh[in >> 1][(in & 1) * 2 + 1]);

            uint32_t bl[2][4];
            #pragma unroll
            for (int p = 0; p < 2; p++) ldsm4(bl[p], bBl + bBase + p * 1280 + koff);
            #pragma unroll
            for (int im = 0; im < 4; im++)
                #pragma unroll
                for (int in = 0; in < 4; in++)
                    mma16816(acc[im][in], ah[im], bl[in >> 1][(in & 1) * 2], bl[in >> 1][(in & 1) * 2 + 1]);

            uint32_t al[4][4];
            #pragma unroll
            for (int im = 0; im < 4; im++) ldsm4(al[im], bAl + aBase + im * 1280 + koff);
            #pragma unroll
            for (int im = 0; im < 4; im++)
                #pragma unroll
                for (int in = 0; in < 4; in++)
                    mma16816(acc[im][in], al[im], bh[in >> 1][(in & 1) * 2], bh[in >> 1][(in & 1) * 2 + 1]);
        }
        __syncthreads();
        if (s + 2 < NST) load_stage(s + 2, buf);
    }

    #pragma unroll
    for (int im = 0; im < 4; im++) {
        int tr = m0 + m_off + im * 16 + (lane >> 2);
        float bias0 = (1.0f - (float)mk[tr])     * NEG_BIG;
        float bias1 = (1.0f - (float)mk[tr + 8]) * NEG_BIG;
        #pragma unroll
        for (int in = 0; in < 4; in++) {
            int col = n0 + n_off + in * 8 + (lane & 3) * 2;
            float2 v0 = {acc[im][in][0] - bias0, acc[im][in][1] - bias0};
            float2 v1 = {acc[im][in][2] - bias1, acc[im][in][3] - bias1};
            *(float2*)&Sp[(size_t)tr * TDEC + col]       = v0;
            *(float2*)&Sp[(size_t)(tr + 8) * TDEC + col] = v1;
        }
    }
}

// ---------------------------------------------------------------------------
// Softmax over t, 3 phases for parallelism.
// Phase A: per (b, 256-t chunk, 16 u): chunk max + sumexp
// ---------------------------------------------------------------------------
__global__ __launch_bounds__(256) void softmaxA_kernel(const float* __restrict__ S)
{
    const int b  = blockIdx.z;
    const int c  = blockIdx.y;            // 0..7
    const int u0 = blockIdx.x * 16;
    const int ux = threadIdx.x;           // 0..15
    const int tz = threadIdx.y;           // 0..15
    const int t0 = c * 256;
    const float* col = S + (size_t)b * TENC * TDEC + u0 + ux;

    float x[16];
    #pragma unroll
    for (int i = 0; i < 16; i++)
        x[i] = col[(size_t)(t0 + tz + i * 16) * TDEC];

    float m = x[0];
    #pragma unroll
    for (int i = 1; i < 16; i++) m = fmaxf(m, x[i]);

    __shared__ float red[16][17];
    red[tz][ux] = m;
    __syncthreads();
    #pragma unroll
    for (int s = 8; s > 0; s >>= 1) {
        if (tz < s) red[tz][ux] = fmaxf(red[tz][ux], red[tz + s][ux]);
        __syncthreads();
    }
    m = red[0][ux];
    __syncthreads();

    float sum = 0.f;
    #pragma unroll
    for (int i = 0; i < 16; i++) sum += __expf(x[i] - m);
    red[tz][ux] = sum;
    __syncthreads();
    #pragma unroll
    for (int s = 8; s > 0; s >>= 1) {
        if (tz < s) red[tz][ux] += red[tz + s][ux];
        __syncthreads();
    }
    if (tz == 0) {
        g_cm[(b * 8 + c) * TDEC + u0 + ux] = m;
        g_cs[(b * 8 + c) * TDEC + u0 + ux] = red[0][ux];
    }
}

// Phase B: combine 8 chunk partials per (b,u)
__global__ void softmaxB_kernel()
{
    int i = blockIdx.x * 256 + threadIdx.x;
    if (i >= BATCH * TDEC) return;
    int b = i / TDEC, u = i % TDEC;
    float M = -3.4e38f;
    #pragma unroll
    for (int c = 0; c < 8; c++) M = fmaxf(M, g_cm[(b * 8 + c) * TDEC + u]);
    float Ssum = 0.f;
    #pragma unroll
    for (int c = 0; c < 8; c++)
        Ssum += g_cs[(b * 8 + c) * TDEC + u] * __expf(g_cm[(b * 8 + c) * TDEC + u] - M);
    g_Mx[i] = M;
    g_Iv[i] = 1.0f / Ssum;
}

// Phase C: normalize -> f32 scores (in place) + bf16 hi/lo for gemm2
__global__ __launch_bounds__(256) void softmaxC_kernel(float* __restrict__ S)
{
    const int b  = blockIdx.z;
    const int c  = blockIdx.y;
    const int u0 = blockIdx.x * 16;
    const int ux = threadIdx.x;
    const int tz = threadIdx.y;
    const int t0 = c * 256;
    const int u  = u0 + ux;

    const float M   = g_Mx[b * TDEC + u];
    const float inv = g_Iv[b * TDEC + u];
    size_t base = (size_t)b * TENC * TDEC + u;
    float* Sp = S + base;
    __nv_bfloat16* ph = g_ph + base;
    __nv_bfloat16* pl = g_pl + base;

    #pragma unroll
    for (int i = 0; i < 16; i++) {
        size_t idx = (size_t)(t0 + tz + i * 16) * TDEC;
        float p = __expf(Sp[idx] - M) * inv;
        Sp[idx] = p;
        __nv_bfloat16 h = __float2bfloat16(p);
        ph[idx] = h;
        pl[idx] = __float2bfloat16(p - __bfloat162float(h));
    }
}

// ---------------------------------------------------------------------------
// GEMM2: ctx[b,u,d] = sum_t p[t,u] * enc[t,d]
// A = p [t][u] -> ldmatrix.trans ; B = enc [t][d] -> ldmatrix.trans
// BM=128(u), BN=128(d), BK=32(t). smem row stride 272 B. Double-buffered.
// ---------------------------------------------------------------------------
#define G2_BUF   8704             // 32 rows * 272 B
#define G2_STAGE (4 * G2_BUF)
#define G2_DYN   (2 * G2_STAGE + 1024)

__global__ __launch_bounds__(256, 2) void gemm2_kernel(float* __restrict__ ctx)
{
    extern __shared__ __align__(16) uint8_t dynsm[];
    const uint32_t dynb = (smem_u32(dynsm) + 1023u) & ~1023u;

    const int b  = blockIdx.z;
    const int u0 = blockIdx.y * 128;
    const int d0 = blockIdx.x * 128;

    const __nv_bfloat16* Ph = g_ph + (size_t)b * TENC * TDEC;
    const __nv_bfloat16* Pl = g_pl + (size_t)b * TENC * TDEC;
    const __nv_bfloat16* Eh = g_eh + (size_t)b * TENC * DIM;
    const __nv_bfloat16* El = g_el + (size_t)b * TENC * DIM;
    float* C = ctx + (size_t)b * TDEC * DIM;

    const int tid  = threadIdx.x;
    const int lane = tid & 31;
    const int wid  = tid >> 5;
    const int m_off = (wid & 1) * 64;   // u
    const int n_off = (wid >> 1) * 32;  // d

    const int lrow = tid >> 4;   // 0..15 (+16)
    const int lc   = tid & 15;

    const uint32_t aBase = (uint32_t)(((lane & 7) + ((lane >> 4) << 3)) * 272
                                      + (m_off + ((lane >> 3) & 1) * 8) * 2);
    const uint32_t bBase = (uint32_t)(((lane & 7) + (((lane >> 3) & 1) << 3)) * 272
                                      + (n_off + (lane >> 4) * 8) * 2);

    float acc[4][4][4];
    #pragma unroll
    for (int i = 0; i < 4; i++)
        #pragma unroll
        for (int j = 0; j < 4; j++)
            #pragma unroll
            for (int k = 0; k < 4; k++) acc[i][j][k] = 0.f;

    const int NST = TENC / 32;

    auto load_stage = [&](int s, int buf) {
        const int k0 = s * 32;
        const uint32_t sb = dynb + (uint32_t)buf * G2_STAGE;
        #pragma unroll
        for (int j = 0; j < 2; j++) {
            int row = lrow + j * 16;
            uint32_t so = (uint32_t)(row * 272 + lc * 16);
            size_t goP = (size_t)(k0 + row) * TDEC + u0 + lc * 8;
            size_t goE = (size_t)(k0 + row) * DIM + d0 + lc * 8;
            cpa16(sb + so,              Ph + goP);
            cpa16(sb + G2_BUF + so,     Pl + goP);
            cpa16(sb + 2 * G2_BUF + so, Eh + goE);
            cpa16(sb + 3 * G2_BUF + so, El + goE);
        }
        cpa_commit();
    };

    load_stage(0, 0);
    load_stage(1, 1);

    for (int s = 0; s < NST; s++) {
        const int buf = s & 1;
        if (s == NST - 1) cpa_wait0(); else cpa_wait1();
        __syncthreads();

        const uint32_t bPh = dynb + (uint32_t)buf * G2_STAGE;
        const uint32_t bPl = bPh + G2_BUF;
        const uint32_t bEh = bPh + 2 * G2_BUF;
        const uint32_t bEl = bPh + 3 * G2_BUF;

        #pragma unroll
        for (int ks = 0; ks < 2; ks++) {
            uint32_t koff = (uint32_t)(ks * 16 * 272);
            uint32_t ah[4][4], bh[2][4];
            #pragma unroll
            for (int im = 0; im < 4; im++) ldsm4t(ah[im], bPh + aBase + im * 32 + koff);
            #pragma unroll
            for (int p = 0; p < 2; p++)   ldsm4t(bh[p], bEh + bBase + p * 32 + koff);
            #pragma unroll
            for (int im = 0; im < 4; im++)
                #pragma unroll
                for (int in = 0; in < 4; in++)
                    mma16816(acc[im][in], ah[im], bh[in >> 1][(in & 1) * 2], bh[in >> 1][(in & 1) * 2 + 1]);

            uint32_t bl[2][4];
            #pragma unroll
            for (int p = 0; p < 2; p++) ldsm4t(bl[p], bEl + bBase + p * 32 + koff);
            #pragma unroll
            for (int im = 0; im < 4; im++)
                #pragma unroll
                for (int in = 0; in < 4; in++)
                    mma16816(acc[im][in], ah[im], bl[in >> 1][(in & 1) * 2], bl[in >> 1][(in & 1) * 2 + 1]);

            uint32_t al[4][4];
            #pragma unroll
            for (int im = 0; im < 4; im++) ldsm4t(al[im], bPl + aBase + im * 32 + koff);
            #pragma unroll
            for (int im = 0; im < 4; im++)
                #pragma unroll
                for (int in = 0; in < 4; in++)
                    mma16816(acc[im][in], al[im], bh[in >> 1][(in & 1) * 2], bh[in >> 1][(in & 1) * 2 + 1]);
        }
        __syncthreads();
        if (s + 2 < NST) load_stage(s + 2, buf);
    }

    #pragma unroll
    for (int im = 0; im < 4; im++) {
        int ur = u0 + m_off + im * 16 + (lane >> 2);
        #pragma unroll
        for (int in = 0; in < 4; in++) {
            int col = d0 + n_off + in * 8 + (lane & 3) * 2;
            float2 v0 = {acc[im][in][0], acc[im][in][1]};
            float2 v1 = {acc[im][in][2], acc[im][in][3]};
            *(float2*)&C[(size_t)ur * DIM + col]       = v0;
            *(float2*)&C[(size_t)(ur + 8) * DIM + col] = v1;
        }
    }
}

// ---------------------------------------------------------------------------
extern "C" void kernel_launch(void* const* d_in, const int* in_sizes, int n_in,
                              void* d_out, int out_size)
{
    const float* enc      = (const float*)d_in[0];
    const int*   enc_mask = (const int*)  d_in[1];
    const float* dec      = (const float*)d_in[2];

    float* ctx = (float*)d_out;                      // [B, TDEC, DIM]
    float* S   = ctx + (size_t)BATCH * TDEC * DIM;   // [B, TENC, TDEC]

    // unconditional each call (deterministic; no static guards)
    cudaFuncSetAttribute(gemm1_kernel, cudaFuncAttributeMaxDynamicSharedMemorySize, G1_DYN);
    cudaFuncSetAttribute(gemm2_kernel, cudaFuncAttributeMaxDynamicSharedMemorySize, G2_DYN);

    split_enc_kernel<<<1024, 256>>>(enc);
    split_dec_kernel<<<512, 256>>>(dec);

    gemm1_kernel<<<dim3(TDEC / 128, TENC / 128, BATCH), 256, G1_DYN>>>(enc_mask, S);

    softmaxA_kernel<<<dim3(TDEC / 16, 8, BATCH), dim3(16, 16)>>>(S);
    softmaxB_kernel<<<(BATCH * TDEC + 255) / 256, 256>>>();
    softmaxC_kernel<<<dim3(TDEC / 16, 8, BATCH), dim3(16, 16)>>>(S);

    gemm2_kernel<<<dim3(DIM / 128, TDEC / 128, BATCH), 256, G2_DYN>>>(ctx);
}

// round 7
// speedup vs baseline: 2.8294x; 1.0235x over previous
#include <cuda_runtime.h>
#include <cuda_bf16.h>
#include <cstdint>
#include <cstddef>

#define BATCH 8
#define TENC 2048
#define TDEC 512
#define DIM  1024
#define NEG_BIG 1e20f

// ---------------------------------------------------------------------------
// Scratch (static device arrays — no allocation allowed)
// ---------------------------------------------------------------------------
__device__ __nv_bfloat16 g_eh[(size_t)BATCH * TENC * DIM];   // enc hi [b][t][d]
__device__ __nv_bfloat16 g_el[(size_t)BATCH * TENC * DIM];   // enc lo
__device__ __nv_bfloat16 g_dh[(size_t)BATCH * TDEC * DIM];   // dec hi [b][u][d]
__device__ __nv_bfloat16 g_dl[(size_t)BATCH * TDEC * DIM];   // dec lo
__device__ __nv_bfloat16 g_ph[(size_t)BATCH * TENC * TDEC];  // scores hi [b][t][u]
__device__ __nv_bfloat16 g_pl[(size_t)BATCH * TENC * TDEC];  // scores lo
// softmax partials
__device__ float g_cm[BATCH * 8 * TDEC];
__device__ float g_cs[BATCH * 8 * TDEC];
__device__ float g_Mx[BATCH * TDEC];
__device__ float g_Iv[BATCH * TDEC];

// ---------------------------------------------------------------------------
// helpers
// ---------------------------------------------------------------------------
__device__ __forceinline__ uint32_t smem_u32(const void* p) {
    return (uint32_t)__cvta_generic_to_shared(p);
}
__device__ __forceinline__ void cpa16(uint32_t s, const void* g) {
    asm volatile("cp.async.cg.shared.global [%0], [%1], 16;\n" :: "r"(s), "l"(g));
}
__device__ __forceinline__ void cpa_commit() {
    asm volatile("cp.async.commit_group;\n");
}
__device__ __forceinline__ void cpa_wait2() { asm volatile("cp.async.wait_group 2;\n"); }
__device__ __forceinline__ void cpa_wait1() { asm volatile("cp.async.wait_group 1;\n"); }
__device__ __forceinline__ void cpa_wait0() { asm volatile("cp.async.wait_group 0;\n"); }
__device__ __forceinline__ void ldsm4(uint32_t* r, uint32_t a) {
    asm volatile("ldmatrix.sync.aligned.m8n8.x4.shared.b16 {%0,%1,%2,%3}, [%4];\n"
                 : "=r"(r[0]), "=r"(r[1]), "=r"(r[2]), "=r"(r[3]) : "r"(a));
}
__device__ __forceinline__ void ldsm4t(uint32_t* r, uint32_t a) {
    asm volatile("ldmatrix.sync.aligned.m8n8.x4.trans.shared.b16 {%0,%1,%2,%3}, [%4];\n"
                 : "=r"(r[0]), "=r"(r[1]), "=r"(r[2]), "=r"(r[3]) : "r"(a));
}
__device__ __forceinline__ void mma16816(float* c, const uint32_t* a, uint32_t b0, uint32_t b1) {
    asm volatile(
        "mma.sync.aligned.m16n8k16.row.col.f32.bf16.bf16.f32 "
        "{%0,%1,%2,%3},{%4,%5,%6,%7},{%8,%9},{%0,%1,%2,%3};\n"
        : "+f"(c[0]), "+f"(c[1]), "+f"(c[2]), "+f"(c[3])
        : "r"(a[0]), "r"(a[1]), "r"(a[2]), "r"(a[3]), "r"(b0), "r"(b1));
}

// ---------------------------------------------------------------------------
// input splits: f32 -> bf16 hi + lo
// ---------------------------------------------------------------------------
__device__ __forceinline__ void split_body(const float* __restrict__ x,
                                           __nv_bfloat16* __restrict__ h,
                                           __nv_bfloat16* __restrict__ l, int n4) {
    int stride = gridDim.x * blockDim.x;
    for (int i = blockIdx.x * blockDim.x + threadIdx.x; i < n4; i += stride) {
        float4 v = ((const float4*)x)[i];
        __nv_bfloat16 h0 = __float2bfloat16(v.x);
        __nv_bfloat16 h1 = __float2bfloat16(v.y);
        __nv_bfloat16 h2 = __float2bfloat16(v.z);
        __nv_bfloat16 h3 = __float2bfloat16(v.w);
        __nv_bfloat16 l0 = __float2bfloat16(v.x - __bfloat162float(h0));
        __nv_bfloat16 l1 = __float2bfloat16(v.y - __bfloat162float(h1));
        __nv_bfloat16 l2 = __float2bfloat16(v.z - __bfloat162float(h2));
        __nv_bfloat16 l3 = __float2bfloat16(v.w - __bfloat162float(h3));
        __nv_bfloat162 hA = {h0, h1}, hB = {h2, h3}, lA = {l0, l1}, lB = {l2, l3};
        uint2 hv = {*(uint32_t*)&hA, *(uint32_t*)&hB};
        uint2 lv = {*(uint32_t*)&lA, *(uint32_t*)&lB};
        ((uint2*)h)[i] = hv;
        ((uint2*)l)[i] = lv;
    }
}
__global__ void split_enc_kernel(const float* __restrict__ x) {
    split_body(x, g_eh, g_el, (int)((size_t)BATCH * TENC * DIM / 4));
}
__global__ void split_dec_kernel(const float* __restrict__ x) {
    split_body(x, g_dh, g_dl, (int)((size_t)BATCH * TDEC * DIM / 4));
}

// ---------------------------------------------------------------------------
// GEMM1: S[b,t,u] = sum_d enc[t,d]*dec[u,d] - (1-mask[t])*NEG_BIG
// bf16x3 mma.sync m16n8k16. BM=BN=128, BK=32, 8 warps (2m x 4n), 64x32/warp.
// 4-deep cp.async ring, 1 CTA/SM (full register budget), one barrier/stage.
// ---------------------------------------------------------------------------
#define G1_BUF   10240            // one array, one stage: 128 rows * 80 B
#define G1_STAGE (4 * G1_BUF)     // Ah, Al, Bh, Bl
#define G1_DYN   (4 * G1_STAGE + 1024)

__global__ __launch_bounds__(256, 1) void gemm1_kernel(
    const int* __restrict__ enc_mask, float* __restrict__ S)
{
    extern __shared__ __align__(16) uint8_t dynsm[];
    const uint32_t dynb = (smem_u32(dynsm) + 1023u) & ~1023u;

    const int b  = blockIdx.z;
    const int m0 = blockIdx.y * 128;   // t
    const int n0 = blockIdx.x * 128;   // u

    const __nv_bfloat16* Ah = g_eh + (size_t)b * TENC * DIM;
    const __nv_bfloat16* Al = g_el + (size_t)b * TENC * DIM;
    const __nv_bfloat16* Bh = g_dh + (size_t)b * TDEC * DIM;
    const __nv_bfloat16* Bl = g_dl + (size_t)b * TDEC * DIM;
    const int* mk = enc_mask + b * TENC;
    float* Sp = S + (size_t)b * TENC * TDEC;

    const int tid  = threadIdx.x;
    const int lane = tid & 31;
    const int wid  = tid >> 5;
    const int m_off = (wid & 1) * 64;
    const int n_off = (wid >> 1) * 32;

    const int lrow = tid >> 2;        // 0..63 (+64 second half)
    const int lc   = tid & 3;

    const uint32_t aBase = (uint32_t)((m_off + (lane & 15)) * 80 + (lane >> 4) * 16);
    const uint32_t bBase = (uint32_t)((n_off + (lane & 7) + ((lane >> 4) << 3)) * 80
                                      + ((lane >> 3) & 1) * 16);

    float acc[4][4][4];
    #pragma unroll
    for (int i = 0; i < 4; i++)
        #pragma unroll
        for (int j = 0; j < 4; j++)
            #pragma unroll
            for (int k = 0; k < 4; k++) acc[i][j][k] = 0.f;

    const int NST = DIM / 32;

    auto load_stage = [&](int s) {
        const int k0 = s * 32;
        const uint32_t sb = dynb + (uint32_t)(s & 3) * G1_STAGE;
        #pragma unroll
        for (int j = 0; j < 2; j++) {
            int row = lrow + j * 64;
            uint32_t so = (uint32_t)(row * 80 + lc * 16);
            size_t goA = (size_t)(m0 + row) * DIM + k0 + lc * 8;
            size_t goB = (size_t)(n0 + row) * DIM + k0 + lc * 8;
            cpa16(sb + so,              Ah + goA);
            cpa16(sb + G1_BUF + so,     Al + goA);
            cpa16(sb + 2 * G1_BUF + so, Bh + goB);
            cpa16(sb + 3 * G1_BUF + so, Bl + goB);
        }
        cpa_commit();
    };

    load_stage(0);
    load_stage(1);
    load_stage(2);

    for (int s = 0; s < NST; s++) {
        if (s < NST - 2) cpa_wait2();
        else if (s == NST - 2) cpa_wait1();
        else cpa_wait0();
        __syncthreads();

        const uint32_t bAh = dynb + (uint32_t)(s & 3) * G1_STAGE;
        const uint32_t bAl = bAh + G1_BUF;
        const uint32_t bBh = bAh + 2 * G1_BUF;
        const uint32_t bBl = bAh + 3 * G1_BUF;

        #pragma unroll
        for (int ks = 0; ks < 2; ks++) {
            uint32_t koff = (uint32_t)(ks * 32);
            uint32_t ah[4][4], bh[2][4];
            #pragma unroll
            for (int im = 0; im < 4; im++) ldsm4(ah[im], bAh + aBase + im * 1280 + koff);
            #pragma unroll
            for (int p = 0; p < 2; p++)   ldsm4(bh[p], bBh + bBase + p * 1280 + koff);
            #pragma unroll
            for (int im = 0; im < 4; im++)
                #pragma unroll
                for (int in = 0; in < 4; in++)
                    mma16816(acc[im][in], ah[im], bh[in >> 1][(in & 1) * 2], bh[in >> 1][(in & 1) * 2 + 1]);

            uint32_t bl[2][4];
            #pragma unroll
            for (int p = 0; p < 2; p++) ldsm4(bl[p], bBl + bBase + p * 1280 + koff);
            #pragma unroll
            for (int im = 0; im < 4; im++)
                #pragma unroll
                for (int in = 0; in < 4; in++)
                    mma16816(acc[im][in], ah[im], bl[in >> 1][(in & 1) * 2], bl[in >> 1][(in & 1) * 2 + 1]);

            uint32_t al[4][4];
            #pragma unroll
            for (int im = 0; im < 4; im++) ldsm4(al[im], bAl + aBase + im * 1280 + koff);
            #pragma unroll
            for (int im = 0; im < 4; im++)
                #pragma unroll
                for (int in = 0; in < 4; in++)
                    mma16816(acc[im][in], al[im], bh[in >> 1][(in & 1) * 2], bh[in >> 1][(in & 1) * 2 + 1]);
        }
        if (s + 3 < NST) load_stage(s + 3);
    }

    #pragma unroll
    for (int im = 0; im < 4; im++) {
        int tr = m0 + m_off + im * 16 + (lane >> 2);
        float bias0 = (1.0f - (float)mk[tr])     * NEG_BIG;
        float bias1 = (1.0f - (float)mk[tr + 8]) * NEG_BIG;
        #pragma unroll
        for (int in = 0; in < 4; in++) {
            int col = n0 + n_off + in * 8 + (lane & 3) * 2;
            float2 v0 = {acc[im][in][0] - bias0, acc[im][in][1] - bias0};
            float2 v1 = {acc[im][in][2] - bias1, acc[im][in][3] - bias1};
            *(float2*)&Sp[(size_t)tr * TDEC + col]       = v0;
            *(float2*)&Sp[(size_t)(tr + 8) * TDEC + col] = v1;
        }
    }
}

// ---------------------------------------------------------------------------
// Softmax over t, 3 phases.
// ---------------------------------------------------------------------------
__global__ __launch_bounds__(256) void softmaxA_kernel(const float* __restrict__ S)
{
    const int b  = blockIdx.z;
    const int c  = blockIdx.y;            // 0..7
    const int u0 = blockIdx.x * 16;
    const int ux = threadIdx.x;           // 0..15
    const int tz = threadIdx.y;           // 0..15
    const int t0 = c * 256;
    const float* col = S + (size_t)b * TENC * TDEC + u0 + ux;

    float x[16];
    #pragma unroll
    for (int i = 0; i < 16; i++)
        x[i] = col[(size_t)(t0 + tz + i * 16) * TDEC];

    float m = x[0];
    #pragma unroll
    for (int i = 1; i < 16; i++) m = fmaxf(m, x[i]);

    __shared__ float red[16][17];
    red[tz][ux] = m;
    __syncthreads();
    #pragma unroll
    for (int s = 8; s > 0; s >>= 1) {
        if (tz < s) red[tz][ux] = fmaxf(red[tz][ux], red[tz + s][ux]);
        __syncthreads();
    }
    m = red[0][ux];
    __syncthreads();

    float sum = 0.f;
    #pragma unroll
    for (int i = 0; i < 16; i++) sum += __expf(x[i] - m);
    red[tz][ux] = sum;
    __syncthreads();
    #pragma unroll
    for (int s = 8; s > 0; s >>= 1) {
        if (tz < s) red[tz][ux] += red[tz + s][ux];
        __syncthreads();
    }
    if (tz == 0) {
        g_cm[(b * 8 + c) * TDEC + u0 + ux] = m;
        g_cs[(b * 8 + c) * TDEC + u0 + ux] = red[0][ux];
    }
}

__global__ void softmaxB_kernel()
{
    int i = blockIdx.x * 256 + threadIdx.x;
    if (i >= BATCH * TDEC) return;
    int b = i / TDEC, u = i % TDEC;
    float M = -3.4e38f;
    #pragma unroll
    for (int c = 0; c < 8; c++) M = fmaxf(M, g_cm[(b * 8 + c) * TDEC + u]);
    float Ssum = 0.f;
    #pragma unroll
    for (int c = 0; c < 8; c++)
        Ssum += g_cs[(b * 8 + c) * TDEC + u] * __expf(g_cm[(b * 8 + c) * TDEC + u] - M);
    g_Mx[i] = M;
    g_Iv[i] = 1.0f / Ssum;
}

__global__ __launch_bounds__(256) void softmaxC_kernel(float* __restrict__ S)
{
    const int b  = blockIdx.z;
    const int c  = blockIdx.y;
    const int u0 = blockIdx.x * 16;
    const int ux = threadIdx.x;
    const int tz = threadIdx.y;
    const int t0 = c * 256;
    const int u  = u0 + ux;

    const float M   = g_Mx[b * TDEC + u];
    const float inv = g_Iv[b * TDEC + u];
    size_t base = (size_t)b * TENC * TDEC + u;
    float* Sp = S + base;
    __nv_bfloat16* ph = g_ph + base;
    __nv_bfloat16* pl = g_pl + base;

    #pragma unroll
    for (int i = 0; i < 16; i++) {
        size_t idx = (size_t)(t0 + tz + i * 16) * TDEC;
        float p = __expf(Sp[idx] - M) * inv;
        Sp[idx] = p;
        __nv_bfloat16 h = __float2bfloat16(p);
        ph[idx] = h;
        pl[idx] = __float2bfloat16(p - __bfloat162float(h));
    }
}

// ---------------------------------------------------------------------------
// GEMM2: ctx[b,u,d] = sum_t p[t,u] * enc[t,d]
// A = p [t][u] -> ldmatrix.trans ; B = enc [t][d] -> ldmatrix.trans
// BM=128(u), BN=128(d), BK=32(t). 4-deep ring, 1 CTA/SM, one barrier/stage.
// ---------------------------------------------------------------------------
#define G2_BUF   8704             // 32 rows * 272 B
#define G2_STAGE (4 * G2_BUF)
#define G2_DYN   (4 * G2_STAGE + 1024)

__global__ __launch_bounds__(256, 1) void gemm2_kernel(float* __restrict__ ctx)
{
    extern __shared__ __align__(16) uint8_t dynsm[];
    const uint32_t dynb = (smem_u32(dynsm) + 1023u) & ~1023u;

    const int b  = blockIdx.z;
    const int u0 = blockIdx.y * 128;
    const int d0 = blockIdx.x * 128;

    const __nv_bfloat16* Ph = g_ph + (size_t)b * TENC * TDEC;
    const __nv_bfloat16* Pl = g_pl + (size_t)b * TENC * TDEC;
    const __nv_bfloat16* Eh = g_eh + (size_t)b * TENC * DIM;
    const __nv_bfloat16* El = g_el + (size_t)b * TENC * DIM;
    float* C = ctx + (size_t)b * TDEC * DIM;

    const int tid  = threadIdx.x;
    const int lane = tid & 31;
    const int wid  = tid >> 5;
    const int m_off = (wid & 1) * 64;   // u
    const int n_off = (wid >> 1) * 32;  // d

    const int lrow = tid >> 4;   // 0..15 (+16)
    const int lc   = tid & 15;

    const uint32_t aBase = (uint32_t)(((lane & 7) + ((lane >> 4) << 3)) * 272
                                      + (m_off + ((lane >> 3) & 1) * 8) * 2);
    const uint32_t bBase = (uint32_t)(((lane & 7) + (((lane >> 3) & 1) << 3)) * 272
                                      + (n_off + (lane >> 4) * 8) * 2);

    float acc[4][4][4];
    #pragma unroll
    for (int i = 0; i < 4; i++)
        #pragma unroll
        for (int j = 0; j < 4; j++)
            #pragma unroll
            for (int k = 0; k < 4; k++) acc[i][j][k] = 0.f;

    const int NST = TENC / 32;

    auto load_stage = [&](int s) {
        const int k0 = s * 32;
        const uint32_t sb = dynb + (uint32_t)(s & 3) * G2_STAGE;
        #pragma unroll
        for (int j = 0; j < 2; j++) {
            int row = lrow + j * 16;
            uint32_t so = (uint32_t)(row * 272 + lc * 16);
            size_t goP = (size_t)(k0 + row) * TDEC + u0 + lc * 8;
            size_t goE = (size_t)(k0 + row) * DIM + d0 + lc * 8;
            cpa16(sb + so,              Ph + goP);
            cpa16(sb + G2_BUF + so,     Pl + goP);
            cpa16(sb + 2 * G2_BUF + so, Eh + goE);
            cpa16(sb + 3 * G2_BUF + so, El + goE);
        }
        cpa_commit();
    };

    load_stage(0);
    load_stage(1);
    load_stage(2);

    for (int s = 0; s < NST; s++) {
        if (s < NST - 2) cpa_wait2();
        else if (s == NST - 2) cpa_wait1();
        else cpa_wait0();
        __syncthreads();

        const uint32_t bPh = dynb + (uint32_t)(s & 3) * G2_STAGE;
        const uint32_t bPl = bPh + G2_BUF;
        const uint32_t bEh = bPh + 2 * G2_BUF;
        const uint32_t bEl = bPh + 3 * G2_BUF;

        #pragma unroll
        for (int ks = 0; ks < 2; ks++) {
            uint32_t koff = (uint32_t)(ks * 16 * 272);
            uint32_t ah[4][4], bh[2][4];
            #pragma unroll
            for (int im = 0; im < 4; im++) ldsm4t(ah[im], bPh + aBase + im * 32 + koff);
            #pragma unroll
            for (int p = 0; p < 2; p++)   ldsm4t(bh[p], bEh + bBase + p * 32 + koff);
            #pragma unroll
            for (int im = 0; im < 4; im++)
                #pragma unroll
                for (int in = 0; in < 4; in++)
                    mma16816(acc[im][in], ah[im], bh[in >> 1][(in & 1) * 2], bh[in >> 1][(in & 1) * 2 + 1]);

            uint32_t bl[2][4];
            #pragma unroll
            for (int p = 0; p < 2; p++) ldsm4t(bl[p], bEl + bBase + p * 32 + koff);
            #pragma unroll
            for (int im = 0; im < 4; im++)
                #pragma unroll
                for (int in = 0; in < 4; in++)
                    mma16816(acc[im][in], ah[im], bl[in >> 1][(in & 1) * 2], bl[in >> 1][(in & 1) * 2 + 1]);

            uint32_t al[4][4];
            #pragma unroll
            for (int im = 0; im < 4; im++) ldsm4t(al[im], bPl + aBase + im * 32 + koff);
            #pragma unroll
            for (int im = 0; im < 4; im++)
                #pragma unroll
                for (int in = 0; in < 4; in++)
                    mma16816(acc[im][in], al[im], bh[in >> 1][(in & 1) * 2], bh[in >> 1][(in & 1) * 2 + 1]);
        }
        if (s + 3 < NST) load_stage(s + 3);
    }

    #pragma unroll
    for (int im = 0; im < 4; im++) {
        int ur = u0 + m_off + im * 16 + (lane >> 2);
        #pragma unroll
        for (int in = 0; in < 4; in++) {
            int col = d0 + n_off + in * 8 + (lane & 3) * 2;
            float2 v0 = {acc[im][in][0], acc[im][in][1]};
            float2 v1 = {acc[im][in][2], acc[im][in][3]};
            *(float2*)&C[(size_t)ur * DIM + col]       = v0;
            *(float2*)&C[(size_t)(ur + 8) * DIM + col] = v1;
        }
    }
}

// ---------------------------------------------------------------------------
extern "C" void kernel_launch(void* const* d_in, const int* in_sizes, int n_in,
                              void* d_out, int out_size)
{
    const float* enc      = (const float*)d_in[0];
    const int*   enc_mask = (const int*)  d_in[1];
    const float* dec      = (const float*)d_in[2];

    float* ctx = (float*)d_out;                      // [B, TDEC, DIM]
    float* S   = ctx + (size_t)BATCH * TDEC * DIM;   // [B, TENC, TDEC]

    cudaFuncSetAttribute(gemm1_kernel, cudaFuncAttributeMaxDynamicSharedMemorySize, G1_DYN);
    cudaFuncSetAttribute(gemm2_kernel, cudaFuncAttributeMaxDynamicSharedMemorySize, G2_DYN);

    split_enc_kernel<<<1024, 256>>>(enc);
    split_dec_kernel<<<512, 256>>>(dec);

    gemm1_kernel<<<dim3(TDEC / 128, TENC / 128, BATCH), 256, G1_DYN>>>(enc_mask, S);

    softmaxA_kernel<<<dim3(TDEC / 16, 8, BATCH), dim3(16, 16)>>>(S);
    softmaxB_kernel<<<(BATCH * TDEC + 255) / 256, 256>>>();
    softmaxC_kernel<<<dim3(TDEC / 16, 8, BATCH), dim3(16, 16)>>>(S);

    gemm2_kernel<<<dim3(DIM / 128, TDEC / 128, BATCH), 256, G2_DYN>>>(ctx);
}

// round 8
// speedup vs baseline: 3.1444x; 1.1113x over previous
#include <cuda_runtime.h>
#include <cuda_bf16.h>
#include <cuda_fp16.h>
#include <cstdint>
#include <cstddef>

#define BATCH 8
#define TENC 2048
#define TDEC 512
#define DIM  1024
#define NEG_BIG 1e20f

// ---------------------------------------------------------------------------
// Scratch (static device arrays — no allocation allowed)
// ---------------------------------------------------------------------------
__device__ __nv_bfloat16 g_eh[(size_t)BATCH * TENC * DIM];   // enc hi bf16 [b][t][d]
__device__ __nv_bfloat16 g_el[(size_t)BATCH * TENC * DIM];   // enc lo bf16
__device__ __half        g_ef[(size_t)BATCH * TENC * DIM];   // enc fp16 (gemm2)
__device__ __nv_bfloat16 g_dh[(size_t)BATCH * TDEC * DIM];   // dec hi bf16 [b][u][d]
__device__ __nv_bfloat16 g_dl[(size_t)BATCH * TDEC * DIM];   // dec lo bf16
__device__ __half        g_ph[(size_t)BATCH * TENC * TDEC];  // scores hi fp16 [b][t][u]
__device__ __half        g_pl[(size_t)BATCH * TENC * TDEC];  // scores lo fp16
// softmax partials
__device__ float g_cm[BATCH * 8 * TDEC];
__device__ float g_cs[BATCH * 8 * TDEC];

// ---------------------------------------------------------------------------
// helpers
// ---------------------------------------------------------------------------
__device__ __forceinline__ uint32_t smem_u32(const void* p) {
    return (uint32_t)__cvta_generic_to_shared(p);
}
__device__ __forceinline__ void cpa16(uint32_t s, const void* g) {
    asm volatile("cp.async.cg.shared.global [%0], [%1], 16;\n" :: "r"(s), "l"(g));
}
__device__ __forceinline__ void cpa_commit() {
    asm volatile("cp.async.commit_group;\n");
}
__device__ __forceinline__ void cpa_wait2() { asm volatile("cp.async.wait_group 2;\n"); }
__device__ __forceinline__ void cpa_wait1() { asm volatile("cp.async.wait_group 1;\n"); }
__device__ __forceinline__ void cpa_wait0() { asm volatile("cp.async.wait_group 0;\n"); }
__device__ __forceinline__ void ldsm4(uint32_t* r, uint32_t a) {
    asm volatile("ldmatrix.sync.aligned.m8n8.x4.shared.b16 {%0,%1,%2,%3}, [%4];\n"
                 : "=r"(r[0]), "=r"(r[1]), "=r"(r[2]), "=r"(r[3]) : "r"(a));
}
__device__ __forceinline__ void ldsm4t(uint32_t* r, uint32_t a) {
    asm volatile("ldmatrix.sync.aligned.m8n8.x4.trans.shared.b16 {%0,%1,%2,%3}, [%4];\n"
                 : "=r"(r[0]), "=r"(r[1]), "=r"(r[2]), "=r"(r[3]) : "r"(a));
}
__device__ __forceinline__ void mma_bf16(float* c, const uint32_t* a, uint32_t b0, uint32_t b1) {
    asm volatile(
        "mma.sync.aligned.m16n8k16.row.col.f32.bf16.bf16.f32 "
        "{%0,%1,%2,%3},{%4,%5,%6,%7},{%8,%9},{%0,%1,%2,%3};\n"
        : "+f"(c[0]), "+f"(c[1]), "+f"(c[2]), "+f"(c[3])
        : "r"(a[0]), "r"(a[1]), "r"(a[2]), "r"(a[3]), "r"(b0), "r"(b1));
}
__device__ __forceinline__ void mma_fp16(float* c, const uint32_t* a, uint32_t b0, uint32_t b1) {
    asm volatile(
        "mma.sync.aligned.m16n8k16.row.col.f32.f16.f16.f32 "
        "{%0,%1,%2,%3},{%4,%5,%6,%7},{%8,%9},{%0,%1,%2,%3};\n"
        : "+f"(c[0]), "+f"(c[1]), "+f"(c[2]), "+f"(c[3])
        : "r"(a[0]), "r"(a[1]), "r"(a[2]), "r"(a[3]), "r"(b0), "r"(b1));
}

// ---------------------------------------------------------------------------
// enc split: f32 -> bf16 hi/lo + fp16 copy
// ---------------------------------------------------------------------------
__global__ void split_enc_kernel(const float* __restrict__ x)
{
    const int n4 = (int)((size_t)BATCH * TENC * DIM / 4);
    int stride = gridDim.x * blockDim.x;
    for (int i = blockIdx.x * blockDim.x + threadIdx.x; i < n4; i += stride) {
        float4 v = ((const float4*)x)[i];
        __nv_bfloat16 h0 = __float2bfloat16(v.x), h1 = __float2bfloat16(v.y);
        __nv_bfloat16 h2 = __float2bfloat16(v.z), h3 = __float2bfloat16(v.w);
        __nv_bfloat16 l0 = __float2bfloat16(v.x - __bfloat162float(h0));
        __nv_bfloat16 l1 = __float2bfloat16(v.y - __bfloat162float(h1));
        __nv_bfloat16 l2 = __float2bfloat16(v.z - __bfloat162float(h2));
        __nv_bfloat16 l3 = __float2bfloat16(v.w - __bfloat162float(h3));
        __nv_bfloat162 hA = {h0, h1}, hB = {h2, h3}, lA = {l0, l1}, lB = {l2, l3};
        uint2 hv = {*(uint32_t*)&hA, *(uint32_t*)&hB};
        uint2 lv = {*(uint32_t*)&lA, *(uint32_t*)&lB};
        ((uint2*)g_eh)[i] = hv;
        ((uint2*)g_el)[i] = lv;
        __half2 fA = {__float2half(v.x), __float2half(v.y)};
        __half2 fB = {__float2half(v.z), __float2half(v.w)};
        uint2 fv = {*(uint32_t*)&fA, *(uint32_t*)&fB};
        ((uint2*)g_ef)[i] = fv;
    }
}

// dec split: bf16 hi/lo only
__global__ void split_dec_kernel(const float* __restrict__ x)
{
    const int n4 = (int)((size_t)BATCH * TDEC * DIM / 4);
    int stride = gridDim.x * blockDim.x;
    for (int i = blockIdx.x * blockDim.x + threadIdx.x; i < n4; i += stride) {
        float4 v = ((const float4*)x)[i];
        __nv_bfloat16 h0 = __float2bfloat16(v.x), h1 = __float2bfloat16(v.y);
        __nv_bfloat16 h2 = __float2bfloat16(v.z), h3 = __float2bfloat16(v.w);
        __nv_bfloat16 l0 = __float2bfloat16(v.x - __bfloat162float(h0));
        __nv_bfloat16 l1 = __float2bfloat16(v.y - __bfloat162float(h1));
        __nv_bfloat16 l2 = __float2bfloat16(v.z - __bfloat162float(h2));
        __nv_bfloat16 l3 = __float2bfloat16(v.w - __bfloat162float(h3));
        __nv_bfloat162 hA = {h0, h1}, hB = {h2, h3}, lA = {l0, l1}, lB = {l2, l3};
        uint2 hv = {*(uint32_t*)&hA, *(uint32_t*)&hB};
        uint2 lv = {*(uint32_t*)&lA, *(uint32_t*)&lB};
        ((uint2*)g_dh)[i] = hv;
        ((uint2*)g_dl)[i] = lv;
    }
}

// ---------------------------------------------------------------------------
// GEMM1: S[b,t,u] = sum_d enc[t,d]*dec[u,d] - (1-mask[t])*NEG_BIG
// bf16x3 mma.sync. BM=BN=128, BK=32, 8 warps, 4-deep cp.async ring, 1 CTA/SM.
// ---------------------------------------------------------------------------
#define G1_BUF   10240
#define G1_STAGE (4 * G1_BUF)
#define G1_DYN   (4 * G1_STAGE + 1024)

__global__ __launch_bounds__(256, 1) void gemm1_kernel(
    const int* __restrict__ enc_mask, float* __restrict__ S)
{
    extern __shared__ __align__(16) uint8_t dynsm[];
    const uint32_t dynb = (smem_u32(dynsm) + 1023u) & ~1023u;

    const int b  = blockIdx.z;
    const int m0 = blockIdx.y * 128;   // t
    const int n0 = blockIdx.x * 128;   // u

    const __nv_bfloat16* Ah = g_eh + (size_t)b * TENC * DIM;
    const __nv_bfloat16* Al = g_el + (size_t)b * TENC * DIM;
    const __nv_bfloat16* Bh = g_dh + (size_t)b * TDEC * DIM;
    const __nv_bfloat16* Bl = g_dl + (size_t)b * TDEC * DIM;
    const int* mk = enc_mask + b * TENC;
    float* Sp = S + (size_t)b * TENC * TDEC;

    const int tid  = threadIdx.x;
    const int lane = tid & 31;
    const int wid  = tid >> 5;
    const int m_off = (wid & 1) * 64;
    const int n_off = (wid >> 1) * 32;

    const int lrow = tid >> 2;
    const int lc   = tid & 3;

    const uint32_t aBase = (uint32_t)((m_off + (lane & 15)) * 80 + (lane >> 4) * 16);
    const uint32_t bBase = (uint32_t)((n_off + (lane & 7) + ((lane >> 4) << 3)) * 80
                                      + ((lane >> 3) & 1) * 16);

    float acc[4][4][4];
    #pragma unroll
    for (int i = 0; i < 4; i++)
        #pragma unroll
        for (int j = 0; j < 4; j++)
            #pragma unroll
            for (int k = 0; k < 4; k++) acc[i][j][k] = 0.f;

    const int NST = DIM / 32;

    auto load_stage = [&](int s) {
        const int k0 = s * 32;
        const uint32_t sb = dynb + (uint32_t)(s & 3) * G1_STAGE;
        #pragma unroll
        for (int j = 0; j < 2; j++) {
            int row = lrow + j * 64;
            uint32_t so = (uint32_t)(row * 80 + lc * 16);
            size_t goA = (size_t)(m0 + row) * DIM + k0 + lc * 8;
            size_t goB = (size_t)(n0 + row) * DIM + k0 + lc * 8;
            cpa16(sb + so,              Ah + goA);
            cpa16(sb + G1_BUF + so,     Al + goA);
            cpa16(sb + 2 * G1_BUF + so, Bh + goB);
            cpa16(sb + 3 * G1_BUF + so, Bl + goB);
        }
        cpa_commit();
    };

    load_stage(0);
    load_stage(1);
    load_stage(2);

    for (int s = 0; s < NST; s++) {
        if (s < NST - 2) cpa_wait2();
        else if (s == NST - 2) cpa_wait1();
        else cpa_wait0();
        __syncthreads();

        const uint32_t bAh = dynb + (uint32_t)(s & 3) * G1_STAGE;
        const uint32_t bAl = bAh + G1_BUF;
        const uint32_t bBh = bAh + 2 * G1_BUF;
        const uint32_t bBl = bAh + 3 * G1_BUF;

        #pragma unroll
        for (int ks = 0; ks < 2; ks++) {
            uint32_t koff = (uint32_t)(ks * 32);
            uint32_t ah[4][4], bh[2][4];
            #pragma unroll
            for (int im = 0; im < 4; im++) ldsm4(ah[im], bAh + aBase + im * 1280 + koff);
            #pragma unroll
            for (int p = 0; p < 2; p++)   ldsm4(bh[p], bBh + bBase + p * 1280 + koff);
            #pragma unroll
            for (int im = 0; im < 4; im++)
                #pragma unroll
                for (int in = 0; in < 4; in++)
                    mma_bf16(acc[im][in], ah[im], bh[in >> 1][(in & 1) * 2], bh[in >> 1][(in & 1) * 2 + 1]);

            uint32_t bl[2][4];
            #pragma unroll
            for (int p = 0; p < 2; p++) ldsm4(bl[p], bBl + bBase + p * 1280 + koff);
            #pragma unroll
            for (int im = 0; im < 4; im++)
                #pragma unroll
                for (int in = 0; in < 4; in++)
                    mma_bf16(acc[im][in], ah[im], bl[in >> 1][(in & 1) * 2], bl[in >> 1][(in & 1) * 2 + 1]);

            uint32_t al[4][4];
            #pragma unroll
            for (int im = 0; im < 4; im++) ldsm4(al[im], bAl + aBase + im * 1280 + koff);
            #pragma unroll
            for (int im = 0; im < 4; im++)
                #pragma unroll
                for (int in = 0; in < 4; in++)
                    mma_bf16(acc[im][in], al[im], bh[in >> 1][(in & 1) * 2], bh[in >> 1][(in & 1) * 2 + 1]);
        }
        if (s + 3 < NST) load_stage(s + 3);
    }

    #pragma unroll
    for (int im = 0; im < 4; im++) {
        int tr = m0 + m_off + im * 16 + (lane >> 2);
        float bias0 = (1.0f - (float)mk[tr])     * NEG_BIG;
        float bias1 = (1.0f - (float)mk[tr + 8]) * NEG_BIG;
        #pragma unroll
        for (int in = 0; in < 4; in++) {
            int col = n0 + n_off + in * 8 + (lane & 3) * 2;
            float2 v0 = {acc[im][in][0] - bias0, acc[im][in][1] - bias0};
            float2 v1 = {acc[im][in][2] - bias1, acc[im][in][3] - bias1};
            *(float2*)&Sp[(size_t)tr * TDEC + col]       = v0;
            *(float2*)&Sp[(size_t)(tr + 8) * TDEC + col] = v1;
        }
    }
}

// ---------------------------------------------------------------------------
// Softmax, 2 kernels.
// Phase A: per (b, 256-t chunk, 16 u): chunk max + sumexp
// ---------------------------------------------------------------------------
__global__ __launch_bounds__(256) void softmaxA_kernel(const float* __restrict__ S)
{
    const int b  = blockIdx.z;
    const int c  = blockIdx.y;            // 0..7
    const int u0 = blockIdx.x * 16;
    const int ux = threadIdx.x;           // 0..15
    const int tz = threadIdx.y;           // 0..15
    const int t0 = c * 256;
    const float* col = S + (size_t)b * TENC * TDEC + u0 + ux;

    float x[16];
    #pragma unroll
    for (int i = 0; i < 16; i++)
        x[i] = col[(size_t)(t0 + tz + i * 16) * TDEC];

    float m = x[0];
    #pragma unroll
    for (int i = 1; i < 16; i++) m = fmaxf(m, x[i]);

    __shared__ float red[16][17];
    red[tz][ux] = m;
    __syncthreads();
    #pragma unroll
    for (int s = 8; s > 0; s >>= 1) {
        if (tz < s) red[tz][ux] = fmaxf(red[tz][ux], red[tz + s][ux]);
        __syncthreads();
    }
    m = red[0][ux];
    __syncthreads();

    float sum = 0.f;
    #pragma unroll
    for (int i = 0; i < 16; i++) sum += __expf(x[i] - m);
    red[tz][ux] = sum;
    __syncthreads();
    #pragma unroll
    for (int s = 8; s > 0; s >>= 1) {
        if (tz < s) red[tz][ux] += red[tz + s][ux];
        __syncthreads();
    }
    if (tz == 0) {
        g_cm[(b * 8 + c) * TDEC + u0 + ux] = m;
        g_cs[(b * 8 + c) * TDEC + u0 + ux] = red[0][ux];
    }
}

// Phase C (absorbs B): combine partials, normalize, write f32 + fp16 hi/lo
__global__ __launch_bounds__(256) void softmaxC_kernel(float* __restrict__ S)
{
    const int b  = blockIdx.z;
    const int c  = blockIdx.y;
    const int u0 = blockIdx.x * 16;
    const int ux = threadIdx.x;
    const int tz = threadIdx.y;
    const int t0 = c * 256;
    const int u  = u0 + ux;

    // combine the 8 chunk partials for this u
    float M = -3.4e38f;
    #pragma unroll
    for (int cc = 0; cc < 8; cc++) M = fmaxf(M, g_cm[(b * 8 + cc) * TDEC + u]);
    float Ssum = 0.f;
    #pragma unroll
    for (int cc = 0; cc < 8; cc++)
        Ssum += g_cs[(b * 8 + cc) * TDEC + u] * __expf(g_cm[(b * 8 + cc) * TDEC + u] - M);
    const float inv = 1.0f / Ssum;

    size_t base = (size_t)b * TENC * TDEC + u;
    float* Sp = S + base;
    __half* ph = g_ph + base;
    __half* pl = g_pl + base;

    #pragma unroll
    for (int i = 0; i < 16; i++) {
        size_t idx = (size_t)(t0 + tz + i * 16) * TDEC;
        float p = __expf(Sp[idx] - M) * inv;
        Sp[idx] = p;
        __half h = __float2half(p);
        ph[idx] = h;
        pl[idx] = __float2half(p - __half2float(h));
    }
}

// ---------------------------------------------------------------------------
// GEMM2 (fp16, 2 passes): ctx[b,u,d] = sum_t p[t,u] * enc[t,d]
// A = p (Ph+Pl fp16) [t][u] -> ldmatrix.trans ; B = enc fp16 [t][d] -> trans
// BM=128(u), BN=128(d), BK=32(t). 4-deep ring, 1 CTA/SM.
// ---------------------------------------------------------------------------
#define G2_BUF   8704             // 32 rows * 272 B
#define G2_STAGE (3 * G2_BUF)     // Ph, Pl, Ef
#define G2_DYN   (4 * G2_STAGE + 1024)

__global__ __launch_bounds__(256, 1) void gemm2_kernel(float* __restrict__ ctx)
{
    extern __shared__ __align__(16) uint8_t dynsm[];
    const uint32_t dynb = (smem_u32(dynsm) + 1023u) & ~1023u;

    const int b  = blockIdx.z;
    const int u0 = blockIdx.y * 128;
    const int d0 = blockIdx.x * 128;

    const __half* Ph = g_ph + (size_t)b * TENC * TDEC;
    const __half* Pl = g_pl + (size_t)b * TENC * TDEC;
    const __half* Ef = g_ef + (size_t)b * TENC * DIM;
    float* C = ctx + (size_t)b * TDEC * DIM;

    const int tid  = threadIdx.x;
    const int lane = tid & 31;
    const int wid  = tid >> 5;
    const int m_off = (wid & 1) * 64;   // u
    const int n_off = (wid >> 1) * 32;  // d

    const int lrow = tid >> 4;   // 0..15 (+16)
    const int lc   = tid & 15;

    const uint32_t aBase = (uint32_t)(((lane & 7) + ((lane >> 4) << 3)) * 272
                                      + (m_off + ((lane >> 3) & 1) * 8) * 2);
    const uint32_t bBase = (uint32_t)(((lane & 7) + (((lane >> 3) & 1) << 3)) * 272
                                      + (n_off + (lane >> 4) * 8) * 2);

    float acc[4][4][4];
    #pragma unroll
    for (int i = 0; i < 4; i++)
        #pragma unroll
        for (int j = 0; j < 4; j++)
            #pragma unroll
            for (int k = 0; k < 4; k++) acc[i][j][k] = 0.f;

    const int NST = TENC / 32;

    auto load_stage = [&](int s) {
        const int k0 = s * 32;
        const uint32_t sb = dynb + (uint32_t)(s & 3) * G2_STAGE;
        #pragma unroll
        for (int j = 0; j < 2; j++) {
            int row = lrow + j * 16;
            uint32_t so = (uint32_t)(row * 272 + lc * 16);
            size_t goP = (size_t)(k0 + row) * TDEC + u0 + lc * 8;
            size_t goE = (size_t)(k0 + row) * DIM + d0 + lc * 8;
            cpa16(sb + so,              Ph + goP);
            cpa16(sb + G2_BUF + so,     Pl + goP);
            cpa16(sb + 2 * G2_BUF + so, Ef + goE);
        }
        cpa_commit();
    };

    load_stage(0);
    load_stage(1);
    load_stage(2);

    for (int s = 0; s < NST; s++) {
        if (s < NST - 2) cpa_wait2();
        else if (s == NST - 2) cpa_wait1();
        else cpa_wait0();
        __syncthreads();

        const uint32_t bPh = dynb + (uint32_t)(s & 3) * G2_STAGE;
        const uint32_t bPl = bPh + G2_BUF;
        const uint32_t bEf = bPh + 2 * G2_BUF;

        #pragma unroll
        for (int ks = 0; ks < 2; ks++) {
            uint32_t koff = (uint32_t)(ks * 16 * 272);
            uint32_t ah[4][4], bh[2][4];
            #pragma unroll
            for (int im = 0; im < 4; im++) ldsm4t(ah[im], bPh + aBase + im * 32 + koff);
            #pragma unroll
            for (int p = 0; p < 2; p++)   ldsm4t(bh[p], bEf + bBase + p * 32 + koff);
            #pragma unroll
            for (int im = 0; im < 4; im++)
                #pragma unroll
                for (int in = 0; in < 4; in++)
                    mma_fp16(acc[im][in], ah[im], bh[in >> 1][(in & 1) * 2], bh[in >> 1][(in & 1) * 2 + 1]);

            uint32_t al[4][4];
            #pragma unroll
            for (int im = 0; im < 4; im++) ldsm4t(al[im], bPl + aBase + im * 32 + koff);
            #pragma unroll
            for (int im = 0; im < 4; im++)
                #pragma unroll
                for (int in = 0; in < 4; in++)
                    mma_fp16(acc[im][in], al[im], bh[in >> 1][(in & 1) * 2], bh[in >> 1][(in & 1) * 2 + 1]);
        }
        if (s + 3 < NST) load_stage(s + 3);
    }

    #pragma unroll
    for (int im = 0; im < 4; im++) {
        int ur = u0 + m_off + im * 16 + (lane >> 2);
        #pragma unroll
        for (int in = 0; in < 4; in++) {
            int col = d0 + n_off + in * 8 + (lane & 3) * 2;
            float2 v0 = {acc[im][in][0], acc[im][in][1]};
            float2 v1 = {acc[im][in][2], acc[im][in][3]};
            *(float2*)&C[(size_t)ur * DIM + col]       = v0;
            *(float2*)&C[(size_t)(ur + 8) * DIM + col] = v1;
        }
    }
}

// ---------------------------------------------------------------------------
extern "C" void kernel_launch(void* const* d_in, const int* in_sizes, int n_in,
                              void* d_out, int out_size)
{
    const float* enc      = (const float*)d_in[0];
    const int*   enc_mask = (const int*)  d_in[1];
    const float* dec      = (const float*)d_in[2];

    float* ctx = (float*)d_out;                      // [B, TDEC, DIM]
    float* S   = ctx + (size_t)BATCH * TDEC * DIM;   // [B, TENC, TDEC]

    cudaFuncSetAttribute(gemm1_kernel, cudaFuncAttributeMaxDynamicSharedMemorySize, G1_DYN);
    cudaFuncSetAttribute(gemm2_kernel, cudaFuncAttributeMaxDynamicSharedMemorySize, G2_DYN);

    split_enc_kernel<<<1024, 256>>>(enc);
    split_dec_kernel<<<512, 256>>>(dec);

    gemm1_kernel<<<dim3(TDEC / 128, TENC / 128, BATCH), 256, G1_DYN>>>(enc_mask, S);

    softmaxA_kernel<<<dim3(TDEC / 16, 8, BATCH), dim3(16, 16)>>>(S);
    softmaxC_kernel<<<dim3(TDEC / 16, 8, BATCH), dim3(16, 16)>>>(S);

    gemm2_kernel<<<dim3(DIM / 128, TDEC / 128, BATCH), 256, G2_DYN>>>(ctx);
}